// round 4
// baseline (speedup 1.0000x reference)
#include <cuda_runtime.h>
#include <math.h>
#include <stdint.h>

#define L2E 1.4426950408889634f

// ---------------- scratch (device globals; no allocation allowed) ----------
__device__ float    g_Wpack[256 * 512];
__device__ float    g_Wh1[8 * 1024 * 512];
__device__ uint32_t g_Wh1t[8 * 4 * 32 * 4096];   // tf32 B-fragment layout [b][h][jc][4096]
__device__ float    g_src1[8 * 4 * 1024];
__device__ float    g_dst1[8 * 4 * 1024];
__device__ float    g_out1[8 * 1024 * 512];
__device__ float    g_Wh2[8 * 1024 * 64];
__device__ uint32_t g_Wh2t[8 * 32 * 2048];       // [b][jc][2048]
__device__ float    g_src2[8 * 1024];
__device__ float    g_dst2[8 * 1024];
__device__ uint32_t g_adjbits[8 * 1024 * 32];    // adj bitmask, 1 bit per edge

// ---------------- helpers ---------------------------------------------------
__device__ __forceinline__ void mma_tf32(float* d, const uint32_t* a, const uint32_t* b) {
    asm volatile(
        "mma.sync.aligned.m16n8k8.row.col.f32.tf32.tf32.f32 "
        "{%0,%1,%2,%3}, {%4,%5,%6,%7}, {%8,%9}, {%0,%1,%2,%3};\n"
        : "+f"(d[0]), "+f"(d[1]), "+f"(d[2]), "+f"(d[3])
        : "r"(a[0]), "r"(a[1]), "r"(a[2]), "r"(a[3]), "r"(b[0]), "r"(b[1]));
}
__device__ __forceinline__ uint32_t f2tf32(float f) {
    uint32_t u;
    asm("cvt.rna.tf32.f32 %0, %1;" : "=r"(u) : "f"(f));
    return u;
}

// ---------------- pack W_heads [4][256][128] -> [256][512] -----------------
__global__ void pack_w(const float* __restrict__ W) {
    int o = blockIdx.x * 256 + threadIdx.x;
    int k = o >> 9, c = o & 511;
    int h = c >> 7, d = c & 127;
    g_Wpack[o] = W[(h * 256 + k) * 128 + d];
}

// ---------------- pack adj -> bitmask --------------------------------------
__global__ void pack_adj(const int* __restrict__ adj) {
    int row = blockIdx.x * 8 + (threadIdx.x >> 5);   // 8192 rows
    int lane = threadIdx.x & 31;
    const int* ap = adj + (size_t)row * 1024;
#pragma unroll 4
    for (int it = 0; it < 32; it++) {
        unsigned m = __ballot_sync(0xffffffffu, ap[it * 32 + lane] > 0);
        if (lane == 0) g_adjbits[row * 32 + it] = m;
    }
}

// ---------------- pack Wh -> tf32 B-fragment gmem layout --------------------
// out[(b*H+h)*32+jc][ o ] where o = (((ks*2+wc)*32+lane)*GRPS + grp)*4 + e,
// t2q=grp*4+e, t=t2q>>1, q=t2q&1, k=8ks+(lane&3)+4q, n=wc*(NT/2)+t*8+(lane>>2)
template <int NT, int H>
__global__ __launch_bounds__(256) void pack_wht(
    const float* __restrict__ Wh, uint32_t* __restrict__ out, int NC)
{
    constexpr int GRPS = NT / 32;
    int blk = blockIdx.x;
    int jc = blk & 31;
    int h  = (blk >> 5) % H;
    int b  = blk / (32 * H);
    __shared__ float S[32][NT + 4];
    int tid = threadIdx.x;
#pragma unroll
    for (int l = 0; l < NT / 32; l++) {
        int idx = tid + l * 256;                  // < NT*8
        int r = idx / (NT / 4), c = (idx % (NT / 4)) * 4;
        float4 v = *reinterpret_cast<const float4*>(
            Wh + ((size_t)(b * 1024 + jc * 32 + r)) * NC + h * NT + c);
        S[r][c] = v.x; S[r][c + 1] = v.y; S[r][c + 2] = v.z; S[r][c + 3] = v.w;
    }
    __syncthreads();
    uint32_t* ob = out + (size_t)blk * (NT * 32);
#pragma unroll
    for (int l = 0; l < NT / 8; l++) {
        int o = tid + l * 256;
        int e = o & 3;
        int chunk = o >> 2;
        int grp = chunk % GRPS, slot = chunk / GRPS;
        int lane = slot & 31, wcks = slot >> 5;
        int wc = wcks & 1, ks = wcks >> 1;
        int t2q = grp * 4 + e, t = t2q >> 1, q = t2q & 1;
        int kl = 8 * ks + (lane & 3) + 4 * q;
        int n = wc * (NT / 2) + t * 8 + (lane >> 2);
        ob[o] = f2tf32(S[kl][n]);
    }
}

// ---------------- cp.async tile copy ----------------------------------------
template <int NT>
__device__ __forceinline__ void cp_tile(uint32_t* bfbuf, const uint32_t* gsrc, int tid) {
    constexpr int GRPS = NT / 32;
    constexpr int STRIDE = NT / 8 + 4;
#pragma unroll
    for (int l = 0; l < (NT * 32 / 4) / 256; l++) {
        int c = tid + l * 256;
        int slot = c / GRPS, grp = c % GRPS;
        uint32_t sa = (uint32_t)__cvta_generic_to_shared(bfbuf + slot * STRIDE + grp * 4);
        asm volatile("cp.async.ca.shared.global [%0], [%1], 16;\n"
                     :: "r"(sa), "l"(gsrc + (size_t)c * 4));
    }
}

// ---------------- tf32 GEMM: C[M,N] = A[M,K] @ B[K,N] (round-3, kept) ------
template <int NT>
__global__ __launch_bounds__(256) void gemm_mma(
    const float* __restrict__ A, const float* __restrict__ B,
    float* __restrict__ C, int M, int N, int K)
{
    constexpr int NTILES = NT / 16;
    __shared__ uint32_t As[64][36];
    __shared__ uint32_t Bs[32][NT + 8];
    int tid = threadIdx.x, warp = tid >> 5, lane = tid & 31;
    int wr = warp >> 1, wc = warp & 1;
    int g = lane >> 2, tg = lane & 3;
    int row0 = blockIdx.y * 64, col0 = blockIdx.x * NT;

    float acc[NTILES][4];
#pragma unroll
    for (int t = 0; t < NTILES; t++)
#pragma unroll
        for (int q = 0; q < 4; q++) acc[t][q] = 0.f;

    int ar = tid >> 2, ak = (tid & 3) * 8;

    for (int k0 = 0; k0 < K; k0 += 32) {
        const float* ap = A + (size_t)(row0 + ar) * K + k0 + ak;
        float4 a0 = *reinterpret_cast<const float4*>(ap);
        float4 a1 = *reinterpret_cast<const float4*>(ap + 4);
        *reinterpret_cast<uint4*>(&As[ar][ak]) =
            make_uint4(f2tf32(a0.x), f2tf32(a0.y), f2tf32(a0.z), f2tf32(a0.w));
        *reinterpret_cast<uint4*>(&As[ar][ak + 4]) =
            make_uint4(f2tf32(a1.x), f2tf32(a1.y), f2tf32(a1.z), f2tf32(a1.w));
#pragma unroll
        for (int l = 0; l < NT / 32; l++) {
            int idx = tid + l * 256;
            int r = idx / (NT / 4), c = (idx % (NT / 4)) * 4;
            float4 w = *reinterpret_cast<const float4*>(B + (size_t)(k0 + r) * N + col0 + c);
            *reinterpret_cast<uint4*>(&Bs[r][c]) =
                make_uint4(f2tf32(w.x), f2tf32(w.y), f2tf32(w.z), f2tf32(w.w));
        }
        __syncthreads();
#pragma unroll
        for (int ks = 0; ks < 4; ks++) {
            int k = ks * 8;
            int r0 = wr * 16 + g;
            uint32_t a[4];
            a[0] = As[r0][k + tg];
            a[1] = As[r0 + 8][k + tg];
            a[2] = As[r0][k + tg + 4];
            a[3] = As[r0 + 8][k + tg + 4];
#pragma unroll
            for (int t = 0; t < NTILES; t++) {
                int n0 = wc * (NT / 2) + t * 8 + g;
                uint32_t bf_[2];
                bf_[0] = Bs[k + tg][n0];
                bf_[1] = Bs[k + tg + 4][n0];
                mma_tf32(acc[t], a, bf_);
            }
        }
        __syncthreads();
    }
    int r0 = wr * 16 + g, r1 = r0 + 8;
#pragma unroll
    for (int t = 0; t < NTILES; t++) {
        int col = col0 + wc * (NT / 2) + t * 8 + tg * 2;
        *reinterpret_cast<float2*>(C + (size_t)(row0 + r0) * N + col) =
            make_float2(acc[t][0], acc[t][1]);
        *reinterpret_cast<float2*>(C + (size_t)(row0 + r1) * N + col) =
            make_float2(acc[t][2], acc[t][3]);
    }
}

// ---------------- src/dst dot kernels ---------------------------------------
__global__ void headdots(const float* __restrict__ Wh1, const float* __restrict__ aH,
                         float* __restrict__ srcO, float* __restrict__ dstO) {
    int g = blockIdx.x * 8 + (threadIdx.x >> 5);
    int lane = threadIdx.x & 31;
    int h = g & 3, bn = g >> 2;
    const float* wp = Wh1 + (size_t)bn * 512 + h * 128;
    const float* as = aH + h * 256;
    float ss = 0.f, ds = 0.f;
#pragma unroll
    for (int k2 = 0; k2 < 4; k2++) {
        float w = wp[lane + k2 * 32];
        ss += w * as[lane + k2 * 32];
        ds += w * as[128 + lane + k2 * 32];
    }
#pragma unroll
    for (int off = 16; off; off >>= 1) {
        ss += __shfl_xor_sync(0xffffffffu, ss, off);
        ds += __shfl_xor_sync(0xffffffffu, ds, off);
    }
    if (lane == 0) {
        int b = bn >> 10, n = bn & 1023;
        srcO[(b * 4 + h) * 1024 + n] = ss;
        dstO[(b * 4 + h) * 1024 + n] = ds;
    }
}

__global__ void outdots(const float* __restrict__ Wh2, const float* __restrict__ aO,
                        float* __restrict__ srcO, float* __restrict__ dstO) {
    int g = blockIdx.x * 8 + (threadIdx.x >> 5);
    int lane = threadIdx.x & 31;
    const float* wp = Wh2 + (size_t)g * 64;
    float ss = 0.f, ds = 0.f;
#pragma unroll
    for (int k2 = 0; k2 < 2; k2++) {
        float w = wp[lane + k2 * 32];
        ss += w * aO[lane + k2 * 32];
        ds += w * aO[64 + lane + k2 * 32];
    }
#pragma unroll
    for (int off = 16; off; off >>= 1) {
        ss += __shfl_xor_sync(0xffffffffu, ss, off);
        ds += __shfl_xor_sync(0xffffffffu, ds, off);
    }
    if (lane == 0) { srcO[g] = ss; dstO[g] = ds; }
}

// ---------------- pipelined fused masked-softmax attention ------------------
// P built straight into A-fragment smem (STS.128); Wh streamed via cp.async
// from pre-packed tf32 fragment gmem; double-buffered, 1 sync per 32-chunk.
template <int NT, bool FC>
__global__ __launch_bounds__(256) void attn_pipe(
    const uint32_t* __restrict__ adjbits,
    const float* __restrict__ src, const float* __restrict__ dst,
    const uint32_t* __restrict__ Wht, float* __restrict__ out,
    int NC, int HH, const float* __restrict__ Wf, const float* __restrict__ bfv)
{
    constexpr int NTILES = NT / 16;
    constexpr int GRPS = NT / 32;
    constexpr int STRIDE = NT / 8 + 4;
    constexpr int BF_HALF = 4 * 2 * 32 * STRIDE;     // one buffer, u32
    constexpr int PA_HALF = 4 * 4 * 32 * 4;          // one buffer, u32 (2048)
    extern __shared__ __align__(16) uint32_t dyn[];
    uint32_t* Bf = dyn;                              // [2][ks][wc][lane][STRIDE]
    uint32_t* Pa = dyn + 2 * BF_HALF;                // [2][ks][wr][lane][4]
    float* dstS  = (float*)(dyn + 2 * BF_HALF + 2 * PA_HALF);  // [1024]
    __shared__ float rowsum[64];

    int b = blockIdx.z;
    int row0 = blockIdx.y * 64;
    int col0 = blockIdx.x * NT;
    int h = col0 >> 7;
    int sb = (b * HH + h) * 1024;
    int tid = threadIdx.x, warp = tid >> 5, lane = tid & 31;
    int g = lane >> 2, tg = lane & 3;
    // builder role
    int ks2 = warp >> 2;
    int bwr = warp & 3;
    int br0 = bwr * 16 + g, br1 = br0 + 8;
    // mma role
    int mwr = warp >> 1, mwc = warp & 1;
    int mr0 = mwr * 16 + g;

    float srcv0 = src[sb + row0 + br0];
    float srcv1 = src[sb + row0 + br1];

    {   // preload dst row + zero rowsum
        float4 dv = *reinterpret_cast<const float4*>(dst + sb + tid * 4);
        *reinterpret_cast<float4*>(dstS + tid * 4) = dv;
    }
    if (tid < 64) rowsum[tid] = 0.f;

    const uint32_t* bitrow0 = adjbits + ((size_t)(b * 1024 + row0 + br0)) * 32;
    const uint32_t* bitrow1 = adjbits + ((size_t)(b * 1024 + row0 + br1)) * 32;
    const uint32_t* wbase = Wht + (size_t)((b * HH + h) * 32) * (NT * 32);

    float acc[NTILES][4];
#pragma unroll
    for (int t = 0; t < NTILES; t++)
#pragma unroll
        for (int q = 0; q < 4; q++) acc[t][q] = 0.f;
    float ps0 = 0.f, ps1 = 0.f;

    uint32_t aw0 = bitrow0[0], aw1 = bitrow1[0];

    // prologue: prefetch B chunks 0 and 1
    cp_tile<NT>(Bf, wbase, tid);
    asm volatile("cp.async.commit_group;\n");
    cp_tile<NT>(Bf + BF_HALF, wbase + NT * 32, tid);
    asm volatile("cp.async.commit_group;\n");
    __syncthreads();                                   // dstS / rowsum ready

    // build chunk 0 into Pa[0]
    auto buildChunk = [&](int bufsel, uint32_t w0, uint32_t w1, int jbase) {
        uint32_t* pa = Pa + bufsel * PA_HALF;
#pragma unroll
        for (int kk = 0; kk < 2; kk++) {
            int ks = ks2 * 2 + kk;
            int c0 = 8 * ks + tg;
            float d0 = dstS[jbase + c0], d1 = dstS[jbase + c0 + 4];
            float v, e, p00, p01, p10, p11;
            v = srcv0 + d0; e = v >= 0.f ? v : 0.2f * v;
            p00 = ((w0 >> c0) & 1u) ? exp2f(e * L2E) : 0.f;
            v = srcv0 + d1; e = v >= 0.f ? v : 0.2f * v;
            p01 = ((w0 >> (c0 + 4)) & 1u) ? exp2f(e * L2E) : 0.f;
            v = srcv1 + d0; e = v >= 0.f ? v : 0.2f * v;
            p10 = ((w1 >> c0) & 1u) ? exp2f(e * L2E) : 0.f;
            v = srcv1 + d1; e = v >= 0.f ? v : 0.2f * v;
            p11 = ((w1 >> (c0 + 4)) & 1u) ? exp2f(e * L2E) : 0.f;
            ps0 += p00 + p01;
            ps1 += p10 + p11;
            *reinterpret_cast<uint4*>(pa + ((ks * 4 + bwr) * 32 + lane) * 4) =
                make_uint4(f2tf32(p00), f2tf32(p10), f2tf32(p01), f2tf32(p11));
        }
    };

    buildChunk(0, aw0, aw1, 0);
    aw0 = bitrow0[1]; aw1 = bitrow1[1];
    asm volatile("cp.async.wait_group 0;\n");
    __syncthreads();                                   // Pa[0] + both B buffers ready

    for (int i = 0; i < 32; i++) {
        int p = i & 1;
        if (i >= 1 && i < 31) {                        // prefetch B chunk i+1
            cp_tile<NT>(Bf + (p ^ 1) * BF_HALF, wbase + (size_t)(i + 1) * NT * 32, tid);
            asm volatile("cp.async.commit_group;\n");
        }
        if (i < 31) {
            buildChunk(p ^ 1, aw0, aw1, (i + 1) * 32);
            if (i < 30) { aw0 = bitrow0[i + 2]; aw1 = bitrow1[i + 2]; }
        }
        {   // mma on buffers p
            uint32_t* pa = Pa + p * PA_HALF;
            uint32_t* bfb = Bf + p * BF_HALF;
#pragma unroll
            for (int ks = 0; ks < 4; ks++) {
                uint4 av = *reinterpret_cast<const uint4*>(
                    pa + ((ks * 4 + mwr) * 32 + lane) * 4);
                uint32_t a[4] = {av.x, av.y, av.z, av.w};
                const uint32_t* bp = bfb + ((ks * 2 + mwc) * 32 + lane) * STRIDE;
#pragma unroll
                for (int grp = 0; grp < GRPS; grp++) {
                    uint4 bv = *reinterpret_cast<const uint4*>(bp + grp * 4);
                    uint32_t b0[2] = {bv.x, bv.y};
                    uint32_t b1[2] = {bv.z, bv.w};
                    mma_tf32(acc[grp * 2], a, b0);
                    mma_tf32(acc[grp * 2 + 1], a, b1);
                }
            }
        }
        asm volatile("cp.async.wait_group 0;\n");
        __syncthreads();
    }

    // softmax denominators: quad-reduce, two atomic contributions per row
    ps0 += __shfl_xor_sync(0xffffffffu, ps0, 1);
    ps0 += __shfl_xor_sync(0xffffffffu, ps0, 2);
    ps1 += __shfl_xor_sync(0xffffffffu, ps1, 1);
    ps1 += __shfl_xor_sync(0xffffffffu, ps1, 2);
    if (tg == 0) {
        atomicAdd(&rowsum[br0], ps0);
        atomicAdd(&rowsum[br1], ps1);
    }
    __syncthreads();
    float s0 = rowsum[mr0], s1 = rowsum[mr0 + 8];
    float inv0 = (s0 > 0.f) ? 1.f / s0 : 0.f;
    float inv1 = (s1 > 0.f) ? 1.f / s1 : 0.f;

    if (!FC) {
#pragma unroll
        for (int t = 0; t < NTILES; t++) {
            int col = col0 + mwc * (NT / 2) + t * 8 + tg * 2;
            *reinterpret_cast<float2*>(out + ((size_t)b * 1024 + row0 + mr0) * NC + col) =
                make_float2(acc[t][0] * inv0, acc[t][1] * inv0);
            *reinterpret_cast<float2*>(out + ((size_t)b * 1024 + row0 + mr0 + 8) * NC + col) =
                make_float2(acc[t][2] * inv1, acc[t][3] * inv1);
        }
    } else {
        // overlay Cs/WfS on dead Bf/Pa region
        float* Cs  = (float*)dyn;                     // [64][68]
        float* WfS = (float*)dyn + 64 * 68;           // [64][68]
        __syncthreads();
#pragma unroll
        for (int l = 0; l < 16; l++) {
            int idx = tid + l * 256;
            WfS[(idx >> 6) * 68 + (idx & 63)] = Wf[idx];
        }
#pragma unroll
        for (int t = 0; t < NTILES; t++) {
            int col = mwc * (NT / 2) + t * 8 + tg * 2;
            float v00 = acc[t][0] * inv0, v01 = acc[t][1] * inv0;
            float v10 = acc[t][2] * inv1, v11 = acc[t][3] * inv1;
            Cs[mr0 * 68 + col]           = (v00 > 0.f) ? v00 : expm1f(v00);
            Cs[mr0 * 68 + col + 1]       = (v01 > 0.f) ? v01 : expm1f(v01);
            Cs[(mr0 + 8) * 68 + col]     = (v10 > 0.f) ? v10 : expm1f(v10);
            Cs[(mr0 + 8) * 68 + col + 1] = (v11 > 0.f) ? v11 : expm1f(v11);
        }
        __syncthreads();
        int row = tid >> 2, c0f = (tid & 3) * 16;
        float o[16];
#pragma unroll
        for (int j = 0; j < 16; j++) o[j] = bfv[c0f + j];
#pragma unroll
        for (int k = 0; k < 64; k++) {
            float cv = Cs[row * 68 + k];
#pragma unroll
            for (int j = 0; j < 16; j++) o[j] += cv * WfS[k * 68 + c0f + j];
        }
        float* op = out + ((size_t)b * 1024 + row0 + row) * 64 + c0f;
#pragma unroll
        for (int jj = 0; jj < 4; jj++)
            *reinterpret_cast<float4*>(op + jj * 4) =
                make_float4(fmaxf(o[jj * 4], 0.f), fmaxf(o[jj * 4 + 1], 0.f),
                            fmaxf(o[jj * 4 + 2], 0.f), fmaxf(o[jj * 4 + 3], 0.f));
    }
}

// ---------------- launch ----------------------------------------------------
extern "C" void kernel_launch(void* const* d_in, const int* in_sizes, int n_in,
                              void* d_out, int out_size)
{
    const float* x       = (const float*)d_in[0];
    const int*   adj     = (const int*)  d_in[1];
    const float* W_heads = (const float*)d_in[2];
    const float* a_heads = (const float*)d_in[3];
    const float* W_out   = (const float*)d_in[4];
    const float* a_out   = (const float*)d_in[5];
    const float* Wf      = (const float*)d_in[6];
    const float* bf      = (const float*)d_in[7];
    float* out = (float*)d_out;

    float *pWpack, *pWh1, *pSrc1, *pDst1, *pOut1, *pWh2, *pSrc2, *pDst2;
    uint32_t *pWh1t, *pWh2t, *pBits;
    cudaGetSymbolAddress((void**)&pWpack, g_Wpack);
    cudaGetSymbolAddress((void**)&pWh1,   g_Wh1);
    cudaGetSymbolAddress((void**)&pWh1t,  g_Wh1t);
    cudaGetSymbolAddress((void**)&pSrc1,  g_src1);
    cudaGetSymbolAddress((void**)&pDst1,  g_dst1);
    cudaGetSymbolAddress((void**)&pOut1,  g_out1);
    cudaGetSymbolAddress((void**)&pWh2,   g_Wh2);
    cudaGetSymbolAddress((void**)&pWh2t,  g_Wh2t);
    cudaGetSymbolAddress((void**)&pSrc2,  g_src2);
    cudaGetSymbolAddress((void**)&pDst2,  g_dst2);
    cudaGetSymbolAddress((void**)&pBits,  g_adjbits);

    // dynamic smem sizes
    const int smem128 = (2 * (4 * 2 * 32 * 20) + 2 * 2048 + 1024) * 4;  // 61440 B
    const int smem64  = (2 * (4 * 2 * 32 * 12) + 2 * 2048 + 1024) * 4;  // 45056 B
    static bool attr_done = false;
    if (!attr_done) {
        cudaFuncSetAttribute(attn_pipe<128, false>,
                             cudaFuncAttributeMaxDynamicSharedMemorySize, smem128);
        cudaFuncSetAttribute(attn_pipe<64, true>,
                             cudaFuncAttributeMaxDynamicSharedMemorySize, smem64);
        attr_done = true;
    }

    pack_adj<<<1024, 256>>>(adj);
    // Layer 1
    pack_w<<<512, 256>>>(W_heads);
    gemm_mma<128><<<dim3(4, 128), 256>>>(x, pWpack, pWh1, 8192, 512, 256);
    headdots<<<4096, 256>>>(pWh1, a_heads, pSrc1, pDst1);
    pack_wht<128, 4><<<1024, 256>>>(pWh1, pWh1t, 512);
    attn_pipe<128, false><<<dim3(4, 16, 8), 256, smem128>>>(
        pBits, pSrc1, pDst1, pWh1t, pOut1, 512, 4, nullptr, nullptr);
    // Layer 2
    gemm_mma<64><<<dim3(1, 128), 256>>>(pOut1, W_out, pWh2, 8192, 64, 512);
    outdots<<<1024, 256>>>(pWh2, a_out, pSrc2, pDst2);
    pack_wht<64, 1><<<256, 256>>>(pWh2, pWh2t, 64);
    attn_pipe<64, true><<<dim3(1, 16, 8), 256, smem64>>>(
        pBits, pSrc2, pDst2, pWh2t, out, 64, 1, Wf, bf);
}

// round 5
// speedup vs baseline: 1.1038x; 1.1038x over previous
#include <cuda_runtime.h>
#include <math.h>
#include <stdint.h>

#define L2E 1.4426950408889634f

// ---------------- scratch (device globals; no allocation allowed) ----------
__device__ float    g_Wpack[256 * 512];
__device__ float    g_Wh1[8 * 1024 * 512];
__device__ uint32_t g_Wh1t[8 * 4 * 32 * 4096];   // tf32 B-fragment layout [b][h][jc][4096]
__device__ float    g_src1[8 * 4 * 1024];
__device__ float    g_dst1[8 * 4 * 1024];
__device__ float    g_out1[8 * 1024 * 512];
__device__ float    g_Wh2[8 * 1024 * 64];
__device__ uint32_t g_Wh2t[8 * 32 * 2048];       // [b][jc][2048]
__device__ float    g_src2[8 * 1024];
__device__ float    g_dst2[8 * 1024];
__device__ uint32_t g_adjbits[8 * 1024 * 32];    // adj bitmask, 1 bit per edge

// ---------------- helpers ---------------------------------------------------
__device__ __forceinline__ void mma_tf32(float* d, const uint32_t* a, const uint32_t* b) {
    asm volatile(
        "mma.sync.aligned.m16n8k8.row.col.f32.tf32.tf32.f32 "
        "{%0,%1,%2,%3}, {%4,%5,%6,%7}, {%8,%9}, {%0,%1,%2,%3};\n"
        : "+f"(d[0]), "+f"(d[1]), "+f"(d[2]), "+f"(d[3])
        : "r"(a[0]), "r"(a[1]), "r"(a[2]), "r"(a[3]), "r"(b[0]), "r"(b[1]));
}
__device__ __forceinline__ uint32_t f2tf32(float f) {
    uint32_t u;
    asm("cvt.rna.tf32.f32 %0, %1;" : "=r"(u) : "f"(f));
    return u;
}

// ---------------- pack W_heads [4][256][128] -> [256][512] -----------------
__global__ void pack_w(const float* __restrict__ W) {
    int o = blockIdx.x * 256 + threadIdx.x;
    int k = o >> 9, c = o & 511;
    int h = c >> 7, d = c & 127;
    g_Wpack[o] = W[(h * 256 + k) * 128 + d];
}

// ---------------- pack adj -> bitmask --------------------------------------
__global__ void pack_adj(const int* __restrict__ adj) {
    int row = blockIdx.x * 8 + (threadIdx.x >> 5);   // 8192 rows
    int lane = threadIdx.x & 31;
    const int* ap = adj + (size_t)row * 1024;
#pragma unroll 4
    for (int it = 0; it < 32; it++) {
        unsigned m = __ballot_sync(0xffffffffu, ap[it * 32 + lane] > 0);
        if (lane == 0) g_adjbits[row * 32 + it] = m;
    }
}

// ---------------- pack Wh -> tf32 B-fragment gmem layout --------------------
template <int NT, int H>
__global__ __launch_bounds__(256) void pack_wht(
    const float* __restrict__ Wh, uint32_t* __restrict__ out, int NC)
{
    constexpr int GRPS = NT / 32;
    int blk = blockIdx.x;
    int jc = blk & 31;
    int h  = (blk >> 5) % H;
    int b  = blk / (32 * H);
    __shared__ float S[32][NT + 4];
    int tid = threadIdx.x;
#pragma unroll
    for (int l = 0; l < NT / 32; l++) {
        int idx = tid + l * 256;
        int r = idx / (NT / 4), c = (idx % (NT / 4)) * 4;
        float4 v = *reinterpret_cast<const float4*>(
            Wh + ((size_t)(b * 1024 + jc * 32 + r)) * NC + h * NT + c);
        S[r][c] = v.x; S[r][c + 1] = v.y; S[r][c + 2] = v.z; S[r][c + 3] = v.w;
    }
    __syncthreads();
    uint32_t* ob = out + (size_t)blk * (NT * 32);
#pragma unroll
    for (int l = 0; l < NT / 8; l++) {
        int o = tid + l * 256;
        int e = o & 3;
        int chunk = o >> 2;
        int grp = chunk % GRPS, slot = chunk / GRPS;
        int lane = slot & 31, wcks = slot >> 5;
        int wc = wcks & 1, ks = wcks >> 1;
        int t2q = grp * 4 + e, t = t2q >> 1, q = t2q & 1;
        int kl = 8 * ks + (lane & 3) + 4 * q;
        int n = wc * (NT / 2) + t * 8 + (lane >> 2);
        ob[o] = f2tf32(S[kl][n]);
    }
}

// ---------------- cp.async tile copy ----------------------------------------
template <int NT>
__device__ __forceinline__ void cp_tile(uint32_t* bfbuf, const uint32_t* gsrc, int tid) {
    constexpr int GRPS = NT / 32;
    constexpr int STRIDE = NT / 8 + 4;
#pragma unroll
    for (int l = 0; l < (NT * 32 / 4) / 256; l++) {
        int c = tid + l * 256;
        int slot = c / GRPS, grp = c % GRPS;
        uint32_t sa = (uint32_t)__cvta_generic_to_shared(bfbuf + slot * STRIDE + grp * 4);
        asm volatile("cp.async.ca.shared.global [%0], [%1], 16;\n"
                     :: "r"(sa), "l"(gsrc + (size_t)c * 4));
    }
}

// ---------------- tf32 GEMM: C[M,N] = A[M,K] @ B[K,N] ----------------------
template <int NT>
__global__ __launch_bounds__(256) void gemm_mma(
    const float* __restrict__ A, const float* __restrict__ B,
    float* __restrict__ C, int M, int N, int K)
{
    constexpr int NTILES = NT / 16;
    __shared__ uint32_t As[64][36];
    __shared__ uint32_t Bs[32][NT + 8];
    int tid = threadIdx.x, warp = tid >> 5, lane = tid & 31;
    int wr = warp >> 1, wc = warp & 1;
    int g = lane >> 2, tg = lane & 3;
    int row0 = blockIdx.y * 64, col0 = blockIdx.x * NT;

    float acc[NTILES][4];
#pragma unroll
    for (int t = 0; t < NTILES; t++)
#pragma unroll
        for (int q = 0; q < 4; q++) acc[t][q] = 0.f;

    int ar = tid >> 2, ak = (tid & 3) * 8;

    for (int k0 = 0; k0 < K; k0 += 32) {
        const float* ap = A + (size_t)(row0 + ar) * K + k0 + ak;
        float4 a0 = *reinterpret_cast<const float4*>(ap);
        float4 a1 = *reinterpret_cast<const float4*>(ap + 4);
        *reinterpret_cast<uint4*>(&As[ar][ak]) =
            make_uint4(f2tf32(a0.x), f2tf32(a0.y), f2tf32(a0.z), f2tf32(a0.w));
        *reinterpret_cast<uint4*>(&As[ar][ak + 4]) =
            make_uint4(f2tf32(a1.x), f2tf32(a1.y), f2tf32(a1.z), f2tf32(a1.w));
#pragma unroll
        for (int l = 0; l < NT / 32; l++) {
            int idx = tid + l * 256;
            int r = idx / (NT / 4), c = (idx % (NT / 4)) * 4;
            float4 w = *reinterpret_cast<const float4*>(B + (size_t)(k0 + r) * N + col0 + c);
            *reinterpret_cast<uint4*>(&Bs[r][c]) =
                make_uint4(f2tf32(w.x), f2tf32(w.y), f2tf32(w.z), f2tf32(w.w));
        }
        __syncthreads();
#pragma unroll
        for (int ks = 0; ks < 4; ks++) {
            int k = ks * 8;
            int r0 = wr * 16 + g;
            uint32_t a[4];
            a[0] = As[r0][k + tg];
            a[1] = As[r0 + 8][k + tg];
            a[2] = As[r0][k + tg + 4];
            a[3] = As[r0 + 8][k + tg + 4];
#pragma unroll
            for (int t = 0; t < NTILES; t++) {
                int n0 = wc * (NT / 2) + t * 8 + g;
                uint32_t bf_[2];
                bf_[0] = Bs[k + tg][n0];
                bf_[1] = Bs[k + tg + 4][n0];
                mma_tf32(acc[t], a, bf_);
            }
        }
        __syncthreads();
    }
    int r0 = wr * 16 + g, r1 = r0 + 8;
#pragma unroll
    for (int t = 0; t < NTILES; t++) {
        int col = col0 + wc * (NT / 2) + t * 8 + tg * 2;
        *reinterpret_cast<float2*>(C + (size_t)(row0 + r0) * N + col) =
            make_float2(acc[t][0], acc[t][1]);
        *reinterpret_cast<float2*>(C + (size_t)(row0 + r1) * N + col) =
            make_float2(acc[t][2], acc[t][3]);
    }
}

// ---------------- src/dst dot kernels ---------------------------------------
__global__ void headdots(const float* __restrict__ Wh1, const float* __restrict__ aH,
                         float* __restrict__ srcO, float* __restrict__ dstO) {
    int g = blockIdx.x * 8 + (threadIdx.x >> 5);
    int lane = threadIdx.x & 31;
    int h = g & 3, bn = g >> 2;
    const float* wp = Wh1 + (size_t)bn * 512 + h * 128;
    const float* as = aH + h * 256;
    float ss = 0.f, ds = 0.f;
#pragma unroll
    for (int k2 = 0; k2 < 4; k2++) {
        float w = wp[lane + k2 * 32];
        ss += w * as[lane + k2 * 32];
        ds += w * as[128 + lane + k2 * 32];
    }
#pragma unroll
    for (int off = 16; off; off >>= 1) {
        ss += __shfl_xor_sync(0xffffffffu, ss, off);
        ds += __shfl_xor_sync(0xffffffffu, ds, off);
    }
    if (lane == 0) {
        int b = bn >> 10, n = bn & 1023;
        srcO[(b * 4 + h) * 1024 + n] = ss;
        dstO[(b * 4 + h) * 1024 + n] = ds;
    }
}

__global__ void outdots(const float* __restrict__ Wh2, const float* __restrict__ aO,
                        float* __restrict__ srcO, float* __restrict__ dstO) {
    int g = blockIdx.x * 8 + (threadIdx.x >> 5);
    int lane = threadIdx.x & 31;
    const float* wp = Wh2 + (size_t)g * 64;
    float ss = 0.f, ds = 0.f;
#pragma unroll
    for (int k2 = 0; k2 < 2; k2++) {
        float w = wp[lane + k2 * 32];
        ss += w * aO[lane + k2 * 32];
        ds += w * aO[64 + lane + k2 * 32];
    }
#pragma unroll
    for (int off = 16; off; off >>= 1) {
        ss += __shfl_xor_sync(0xffffffffu, ss, off);
        ds += __shfl_xor_sync(0xffffffffu, ds, off);
    }
    if (lane == 0) { srcO[g] = ss; dstO[g] = ds; }
}

// ---------------- layer-1 attention: M=128 rows/CTA, NT=128, one wave -------
// 256 threads / 8 warps. Each warp: 2 m16 row-tiles x 64 cols (64 acc regs).
// B chunk (128x32 tf32, fragment layout) streamed once per CTA per chunk and
// reused by 128 rows -> half the L2 traffic and half the chip instructions
// of the 64-row version. Grid 4x8x8 = 256 CTAs = one wave at 2 CTAs/SM.
__global__ __launch_bounds__(256, 2) void attn_pipe128(
    const uint32_t* __restrict__ adjbits,
    const float* __restrict__ src, const float* __restrict__ dst,
    const uint32_t* __restrict__ Wht, float* __restrict__ out,
    int NC, int HH)
{
    constexpr int STRIDE = 20;          // 128/8+4
    constexpr int BF_HALF = 4 * 2 * 32 * STRIDE;  // 5120 u32
    constexpr int PA_HALF = 4 * 8 * 32 * 4;       // 4096 u32
    extern __shared__ __align__(16) uint32_t dyn[];
    uint32_t* Bf = dyn;                            // [2][ks][wc][lane][STRIDE]
    uint32_t* Pa = dyn + 2 * BF_HALF;              // [2][ks][mt][lane][4]
    float* dstS  = (float*)(dyn + 2 * BF_HALF + 2 * PA_HALF);  // [1024]
    __shared__ float rowsum[128];

    int b = blockIdx.z;
    int row0 = blockIdx.y * 128;
    int h = blockIdx.x;
    int sb = (b * HH + h) * 1024;
    int tid = threadIdx.x, warp = tid >> 5, lane = tid & 31;
    int g = lane >> 2, tg = lane & 3;
    // builder role: mts {bm, bm+4}, ks pair bks2
    int bm = warp & 3, bks2 = warp >> 2;
    // mma role: mts {mwr, mwr+4}, col half mwc
    int mwr = warp >> 1, mwc = warp & 1;

    float srcv[2][2];
    const uint32_t* bitrow[2][2];
#pragma unroll
    for (int m2 = 0; m2 < 2; m2++) {
#pragma unroll
        for (int hf = 0; hf < 2; hf++) {
            int r = row0 + (bm + m2 * 4) * 16 + g + hf * 8;
            srcv[m2][hf] = src[sb + r];
            bitrow[m2][hf] = adjbits + (size_t)(b * 1024 + r) * 32;
        }
    }
    {
        float4 dv = *reinterpret_cast<const float4*>(dst + sb + tid * 4);
        *reinterpret_cast<float4*>(dstS + tid * 4) = dv;
    }
    if (tid < 128) rowsum[tid] = 0.f;

    const uint32_t* wbase = Wht + (size_t)((b * HH + h) * 32) * 4096;

    float acc[2][8][4];
#pragma unroll
    for (int m2 = 0; m2 < 2; m2++)
#pragma unroll
        for (int t = 0; t < 8; t++)
#pragma unroll
            for (int q = 0; q < 4; q++) acc[m2][t][q] = 0.f;
    float ps[2][2] = {{0.f, 0.f}, {0.f, 0.f}};

    uint32_t aw[2][2];
#pragma unroll
    for (int m2 = 0; m2 < 2; m2++)
#pragma unroll
        for (int hf = 0; hf < 2; hf++) aw[m2][hf] = bitrow[m2][hf][0];

    auto buildChunk = [&](int bufsel, int jbase) {
        uint32_t* pa = Pa + bufsel * PA_HALF;
#pragma unroll
        for (int kk = 0; kk < 2; kk++) {
            int ks = bks2 * 2 + kk;
            int c0 = ks * 8 + tg;
            float d0 = dstS[jbase + c0], d1 = dstS[jbase + c0 + 4];
#pragma unroll
            for (int m2 = 0; m2 < 2; m2++) {
                int mt = bm + m2 * 4;
                float v, e, p00, p01, p10, p11;
                v = srcv[m2][0] + d0; e = v >= 0.f ? v : 0.2f * v;
                p00 = ((aw[m2][0] >> c0) & 1u) ? exp2f(e * L2E) : 0.f;
                v = srcv[m2][0] + d1; e = v >= 0.f ? v : 0.2f * v;
                p01 = ((aw[m2][0] >> (c0 + 4)) & 1u) ? exp2f(e * L2E) : 0.f;
                v = srcv[m2][1] + d0; e = v >= 0.f ? v : 0.2f * v;
                p10 = ((aw[m2][1] >> c0) & 1u) ? exp2f(e * L2E) : 0.f;
                v = srcv[m2][1] + d1; e = v >= 0.f ? v : 0.2f * v;
                p11 = ((aw[m2][1] >> (c0 + 4)) & 1u) ? exp2f(e * L2E) : 0.f;
                ps[m2][0] += p00 + p01;
                ps[m2][1] += p10 + p11;
                *reinterpret_cast<uint4*>(pa + ((ks * 8 + mt) * 32 + lane) * 4) =
                    make_uint4(f2tf32(p00), f2tf32(p10), f2tf32(p01), f2tf32(p11));
            }
        }
    };

    // prologue: prefetch B chunks 0,1; build P chunk 0
    cp_tile<128>(Bf, wbase, tid);
    asm volatile("cp.async.commit_group;\n");
    cp_tile<128>(Bf + BF_HALF, wbase + 4096, tid);
    asm volatile("cp.async.commit_group;\n");
    __syncthreads();                    // dstS ready

    buildChunk(0, 0);
#pragma unroll
    for (int m2 = 0; m2 < 2; m2++)
#pragma unroll
        for (int hf = 0; hf < 2; hf++) aw[m2][hf] = bitrow[m2][hf][1];
    asm volatile("cp.async.wait_group 0;\n");
    __syncthreads();

    for (int i = 0; i < 32; i++) {
        int p = i & 1;
        if (i >= 1 && i < 31) {
            cp_tile<128>(Bf + (p ^ 1) * BF_HALF, wbase + (size_t)(i + 1) * 4096, tid);
            asm volatile("cp.async.commit_group;\n");
        }
        if (i < 31) {
            buildChunk(p ^ 1, (i + 1) * 32);
            if (i < 30) {
#pragma unroll
                for (int m2 = 0; m2 < 2; m2++)
#pragma unroll
                    for (int hf = 0; hf < 2; hf++) aw[m2][hf] = bitrow[m2][hf][i + 2];
            }
        }
        {
            uint32_t* pa = Pa + p * PA_HALF;
            uint32_t* bfb = Bf + p * BF_HALF;
#pragma unroll
            for (int ks = 0; ks < 4; ks++) {
                uint4 av0 = *reinterpret_cast<const uint4*>(
                    pa + ((ks * 8 + mwr) * 32 + lane) * 4);
                uint4 av1 = *reinterpret_cast<const uint4*>(
                    pa + ((ks * 8 + mwr + 4) * 32 + lane) * 4);
                uint32_t a0[4] = {av0.x, av0.y, av0.z, av0.w};
                uint32_t a1[4] = {av1.x, av1.y, av1.z, av1.w};
                const uint32_t* bp = bfb + ((ks * 2 + mwc) * 32 + lane) * STRIDE;
#pragma unroll
                for (int grp = 0; grp < 4; grp++) {
                    uint4 bv = *reinterpret_cast<const uint4*>(bp + grp * 4);
                    uint32_t b0[2] = {bv.x, bv.y};
                    uint32_t b1[2] = {bv.z, bv.w};
                    mma_tf32(acc[0][grp * 2], a0, b0);
                    mma_tf32(acc[0][grp * 2 + 1], a0, b1);
                    mma_tf32(acc[1][grp * 2], a1, b0);
                    mma_tf32(acc[1][grp * 2 + 1], a1, b1);
                }
            }
        }
        asm volatile("cp.async.wait_group 0;\n");
        __syncthreads();
    }

    // softmax denominators
#pragma unroll
    for (int m2 = 0; m2 < 2; m2++)
#pragma unroll
        for (int hf = 0; hf < 2; hf++) {
            float v = ps[m2][hf];
            v += __shfl_xor_sync(0xffffffffu, v, 1);
            v += __shfl_xor_sync(0xffffffffu, v, 2);
            if (tg == 0)
                atomicAdd(&rowsum[(bm + m2 * 4) * 16 + g + hf * 8], v);
        }
    __syncthreads();

#pragma unroll
    for (int m2 = 0; m2 < 2; m2++) {
        int mt = mwr + m2 * 4;
        int lr0 = mt * 16 + g, lr1 = lr0 + 8;
        float s0 = rowsum[lr0], s1 = rowsum[lr1];
        float inv0 = (s0 > 0.f) ? 1.f / s0 : 0.f;
        float inv1 = (s1 > 0.f) ? 1.f / s1 : 0.f;
#pragma unroll
        for (int t = 0; t < 8; t++) {
            int col = h * 128 + mwc * 64 + t * 8 + tg * 2;
            *reinterpret_cast<float2*>(out + ((size_t)b * 1024 + row0 + lr0) * NC + col) =
                make_float2(acc[m2][t][0] * inv0, acc[m2][t][1] * inv0);
            *reinterpret_cast<float2*>(out + ((size_t)b * 1024 + row0 + lr1) * NC + col) =
                make_float2(acc[m2][t][2] * inv1, acc[m2][t][3] * inv1);
        }
    }
}

// ---------------- layer-2 pipelined attention + fused FC (round-4, kept) ---
template <int NT, bool FC>
__global__ __launch_bounds__(256) void attn_pipe(
    const uint32_t* __restrict__ adjbits,
    const float* __restrict__ src, const float* __restrict__ dst,
    const uint32_t* __restrict__ Wht, float* __restrict__ out,
    int NC, int HH, const float* __restrict__ Wf, const float* __restrict__ bfv)
{
    constexpr int NTILES = NT / 16;
    constexpr int GRPS = NT / 32;
    constexpr int STRIDE = NT / 8 + 4;
    constexpr int BF_HALF = 4 * 2 * 32 * STRIDE;
    constexpr int PA_HALF = 4 * 4 * 32 * 4;
    extern __shared__ __align__(16) uint32_t dyn[];
    uint32_t* Bf = dyn;
    uint32_t* Pa = dyn + 2 * BF_HALF;
    float* dstS  = (float*)(dyn + 2 * BF_HALF + 2 * PA_HALF);
    __shared__ float rowsum[64];

    int b = blockIdx.z;
    int row0 = blockIdx.y * 64;
    int col0 = blockIdx.x * NT;
    int h = col0 >> 7;
    int sb = (b * HH + h) * 1024;
    int tid = threadIdx.x, warp = tid >> 5, lane = tid & 31;
    int g = lane >> 2, tg = lane & 3;
    int ks2 = warp >> 2;
    int bwr = warp & 3;
    int br0 = bwr * 16 + g, br1 = br0 + 8;
    int mwr = warp >> 1, mwc = warp & 1;
    int mr0 = mwr * 16 + g;

    float srcv0 = src[sb + row0 + br0];
    float srcv1 = src[sb + row0 + br1];

    {
        float4 dv = *reinterpret_cast<const float4*>(dst + sb + tid * 4);
        *reinterpret_cast<float4*>(dstS + tid * 4) = dv;
    }
    if (tid < 64) rowsum[tid] = 0.f;

    const uint32_t* bitrow0 = adjbits + ((size_t)(b * 1024 + row0 + br0)) * 32;
    const uint32_t* bitrow1 = adjbits + ((size_t)(b * 1024 + row0 + br1)) * 32;
    const uint32_t* wbase = Wht + (size_t)((b * HH + h) * 32) * (NT * 32);

    float acc[NTILES][4];
#pragma unroll
    for (int t = 0; t < NTILES; t++)
#pragma unroll
        for (int q = 0; q < 4; q++) acc[t][q] = 0.f;
    float ps0 = 0.f, ps1 = 0.f;

    uint32_t aw0 = bitrow0[0], aw1 = bitrow1[0];

    cp_tile<NT>(Bf, wbase, tid);
    asm volatile("cp.async.commit_group;\n");
    cp_tile<NT>(Bf + BF_HALF, wbase + NT * 32, tid);
    asm volatile("cp.async.commit_group;\n");
    __syncthreads();

    auto buildChunk = [&](int bufsel, uint32_t w0, uint32_t w1, int jbase) {
        uint32_t* pa = Pa + bufsel * PA_HALF;
#pragma unroll
        for (int kk = 0; kk < 2; kk++) {
            int ks = ks2 * 2 + kk;
            int c0 = 8 * ks + tg;
            float d0 = dstS[jbase + c0], d1 = dstS[jbase + c0 + 4];
            float v, e, p00, p01, p10, p11;
            v = srcv0 + d0; e = v >= 0.f ? v : 0.2f * v;
            p00 = ((w0 >> c0) & 1u) ? exp2f(e * L2E) : 0.f;
            v = srcv0 + d1; e = v >= 0.f ? v : 0.2f * v;
            p01 = ((w0 >> (c0 + 4)) & 1u) ? exp2f(e * L2E) : 0.f;
            v = srcv1 + d0; e = v >= 0.f ? v : 0.2f * v;
            p10 = ((w1 >> c0) & 1u) ? exp2f(e * L2E) : 0.f;
            v = srcv1 + d1; e = v >= 0.f ? v : 0.2f * v;
            p11 = ((w1 >> (c0 + 4)) & 1u) ? exp2f(e * L2E) : 0.f;
            ps0 += p00 + p01;
            ps1 += p10 + p11;
            *reinterpret_cast<uint4*>(pa + ((ks * 4 + bwr) * 32 + lane) * 4) =
                make_uint4(f2tf32(p00), f2tf32(p10), f2tf32(p01), f2tf32(p11));
        }
    };

    buildChunk(0, aw0, aw1, 0);
    aw0 = bitrow0[1]; aw1 = bitrow1[1];
    asm volatile("cp.async.wait_group 0;\n");
    __syncthreads();

    for (int i = 0; i < 32; i++) {
        int p = i & 1;
        if (i >= 1 && i < 31) {
            cp_tile<NT>(Bf + (p ^ 1) * BF_HALF, wbase + (size_t)(i + 1) * NT * 32, tid);
            asm volatile("cp.async.commit_group;\n");
        }
        if (i < 31) {
            buildChunk(p ^ 1, aw0, aw1, (i + 1) * 32);
            if (i < 30) { aw0 = bitrow0[i + 2]; aw1 = bitrow1[i + 2]; }
        }
        {
            uint32_t* pa = Pa + p * PA_HALF;
            uint32_t* bfb = Bf + p * BF_HALF;
#pragma unroll
            for (int ks = 0; ks < 4; ks++) {
                uint4 av = *reinterpret_cast<const uint4*>(
                    pa + ((ks * 4 + mwr) * 32 + lane) * 4);
                uint32_t a[4] = {av.x, av.y, av.z, av.w};
                const uint32_t* bp = bfb + ((ks * 2 + mwc) * 32 + lane) * STRIDE;
#pragma unroll
                for (int grp = 0; grp < GRPS; grp++) {
                    uint4 bv = *reinterpret_cast<const uint4*>(bp + grp * 4);
                    uint32_t b0[2] = {bv.x, bv.y};
                    uint32_t b1[2] = {bv.z, bv.w};
                    mma_tf32(acc[grp * 2], a, b0);
                    mma_tf32(acc[grp * 2 + 1], a, b1);
                }
            }
        }
        asm volatile("cp.async.wait_group 0;\n");
        __syncthreads();
    }

    ps0 += __shfl_xor_sync(0xffffffffu, ps0, 1);
    ps0 += __shfl_xor_sync(0xffffffffu, ps0, 2);
    ps1 += __shfl_xor_sync(0xffffffffu, ps1, 1);
    ps1 += __shfl_xor_sync(0xffffffffu, ps1, 2);
    if (tg == 0) {
        atomicAdd(&rowsum[br0], ps0);
        atomicAdd(&rowsum[br1], ps1);
    }
    __syncthreads();
    float s0 = rowsum[mr0], s1 = rowsum[mr0 + 8];
    float inv0 = (s0 > 0.f) ? 1.f / s0 : 0.f;
    float inv1 = (s1 > 0.f) ? 1.f / s1 : 0.f;

    if (!FC) {
#pragma unroll
        for (int t = 0; t < NTILES; t++) {
            int col = col0 + mwc * (NT / 2) + t * 8 + tg * 2;
            *reinterpret_cast<float2*>(out + ((size_t)b * 1024 + row0 + mr0) * NC + col) =
                make_float2(acc[t][0] * inv0, acc[t][1] * inv0);
            *reinterpret_cast<float2*>(out + ((size_t)b * 1024 + row0 + mr0 + 8) * NC + col) =
                make_float2(acc[t][2] * inv1, acc[t][3] * inv1);
        }
    } else {
        float* Cs  = (float*)dyn;                     // [64][68]
        float* WfS = (float*)dyn + 64 * 68;           // [64][68]
        __syncthreads();
#pragma unroll
        for (int l = 0; l < 16; l++) {
            int idx = tid + l * 256;
            WfS[(idx >> 6) * 68 + (idx & 63)] = Wf[idx];
        }
#pragma unroll
        for (int t = 0; t < NTILES; t++) {
            int col = mwc * (NT / 2) + t * 8 + tg * 2;
            float v00 = acc[t][0] * inv0, v01 = acc[t][1] * inv0;
            float v10 = acc[t][2] * inv1, v11 = acc[t][3] * inv1;
            Cs[mr0 * 68 + col]           = (v00 > 0.f) ? v00 : expm1f(v00);
            Cs[mr0 * 68 + col + 1]       = (v01 > 0.f) ? v01 : expm1f(v01);
            Cs[(mr0 + 8) * 68 + col]     = (v10 > 0.f) ? v10 : expm1f(v10);
            Cs[(mr0 + 8) * 68 + col + 1] = (v11 > 0.f) ? v11 : expm1f(v11);
        }
        __syncthreads();
        int row = tid >> 2, c0f = (tid & 3) * 16;
        float o[16];
#pragma unroll
        for (int j = 0; j < 16; j++) o[j] = bfv[c0f + j];
#pragma unroll
        for (int k = 0; k < 64; k++) {
            float cv = Cs[row * 68 + k];
#pragma unroll
            for (int j = 0; j < 16; j++) o[j] += cv * WfS[k * 68 + c0f + j];
        }
        float* op = out + ((size_t)b * 1024 + row0 + row) * 64 + c0f;
#pragma unroll
        for (int jj = 0; jj < 4; jj++)
            *reinterpret_cast<float4*>(op + jj * 4) =
                make_float4(fmaxf(o[jj * 4], 0.f), fmaxf(o[jj * 4 + 1], 0.f),
                            fmaxf(o[jj * 4 + 2], 0.f), fmaxf(o[jj * 4 + 3], 0.f));
    }
}

// ---------------- launch ----------------------------------------------------
extern "C" void kernel_launch(void* const* d_in, const int* in_sizes, int n_in,
                              void* d_out, int out_size)
{
    const float* x       = (const float*)d_in[0];
    const int*   adj     = (const int*)  d_in[1];
    const float* W_heads = (const float*)d_in[2];
    const float* a_heads = (const float*)d_in[3];
    const float* W_out   = (const float*)d_in[4];
    const float* a_out   = (const float*)d_in[5];
    const float* Wf      = (const float*)d_in[6];
    const float* bf      = (const float*)d_in[7];
    float* out = (float*)d_out;

    float *pWpack, *pWh1, *pSrc1, *pDst1, *pOut1, *pWh2, *pSrc2, *pDst2;
    uint32_t *pWh1t, *pWh2t, *pBits;
    cudaGetSymbolAddress((void**)&pWpack, g_Wpack);
    cudaGetSymbolAddress((void**)&pWh1,   g_Wh1);
    cudaGetSymbolAddress((void**)&pWh1t,  g_Wh1t);
    cudaGetSymbolAddress((void**)&pSrc1,  g_src1);
    cudaGetSymbolAddress((void**)&pDst1,  g_dst1);
    cudaGetSymbolAddress((void**)&pOut1,  g_out1);
    cudaGetSymbolAddress((void**)&pWh2,   g_Wh2);
    cudaGetSymbolAddress((void**)&pWh2t,  g_Wh2t);
    cudaGetSymbolAddress((void**)&pSrc2,  g_src2);
    cudaGetSymbolAddress((void**)&pDst2,  g_dst2);
    cudaGetSymbolAddress((void**)&pBits,  g_adjbits);

    const int smem1 = (2 * 5120 + 2 * 4096 + 1024) * 4;                 // 77824 B
    const int smem2 = (2 * (4 * 2 * 32 * 12) + 2 * 2048 + 1024) * 4;    // 45056 B
    static bool attr_done = false;
    if (!attr_done) {
        cudaFuncSetAttribute(attn_pipe128,
                             cudaFuncAttributeMaxDynamicSharedMemorySize, smem1);
        cudaFuncSetAttribute(attn_pipe<64, true>,
                             cudaFuncAttributeMaxDynamicSharedMemorySize, smem2);
        attr_done = true;
    }

    pack_adj<<<1024, 256>>>(adj);
    // Layer 1
    pack_w<<<512, 256>>>(W_heads);
    gemm_mma<128><<<dim3(4, 128), 256>>>(x, pWpack, pWh1, 8192, 512, 256);
    headdots<<<4096, 256>>>(pWh1, a_heads, pSrc1, pDst1);
    pack_wht<128, 4><<<1024, 256>>>(pWh1, pWh1t, 512);
    attn_pipe128<<<dim3(4, 8, 8), 256, smem1>>>(
        pBits, pSrc1, pDst1, pWh1t, pOut1, 512, 4);
    // Layer 2
    gemm_mma<64><<<dim3(1, 128), 256>>>(pOut1, W_out, pWh2, 8192, 64, 512);
    outdots<<<1024, 256>>>(pWh2, a_out, pSrc2, pDst2);
    pack_wht<64, 1><<<256, 256>>>(pWh2, pWh2t, 64);
    attn_pipe<64, true><<<dim3(1, 16, 8), 256, smem2>>>(
        pBits, pSrc2, pDst2, pWh2t, out, 64, 1, Wf, bf);
}